// round 16
// baseline (speedup 1.0000x reference)
#include <cuda_runtime.h>

#define NUM_NODES 100000
#define NUM_EDGES 6400000
#define NUM_STEPS 10

#define TILE 10000                 // dst nodes per tile (40KB smem acc in spmv)
#define NTILES 10
#define CTAS_PER_TILE 15           // 150 CTAs (R5/R10-proven)
#define STEP_TPB 1024

#define NBINS (NTILES * NUM_NODES) // 1M bins: key = dst_tile*N + src (exact src)
#define RANK_BITS 12               // packed key = bin<<12 | rank (rank << 4096)
#define SCAN_BLK 1024
#define NSB ((NBINS + SCAN_BLK - 1) / SCAN_BLK)   // 977

#define ILP 8
#define GSTRIDE (NUM_EDGES / ILP)  // 800,000 threads; edges {t, t+G, ..., t+7G}

// Scratch (allocation-free rule: __device__ globals)
__device__ uint2 g_edges[NUM_EDGES];              // {bin<<12|rank, src<<14|dl}
__device__ __align__(16) uint2 g_sp2[NUM_EDGES];  // {packed, prob-bits}, sorted
__device__ int   g_bins[NBINS];
__device__ int   g_binptr[NBINS + 1];
__device__ int   g_blocksum[NSB];
__device__ float g_curA[NUM_NODES];
__device__ float g_curB[NUM_NODES];
__device__ float g_surv[NUM_NODES];
__device__ float g_acc[NUM_NODES];
__device__ int   g_is64;

// ---------------------------------------------------------------------------
// Fused prep: detect int64-vs-int32 (block 0), zero bins, init node state.
// ---------------------------------------------------------------------------
__global__ void prep_kernel(const int* __restrict__ w, const float* __restrict__ x) {
    int i = blockIdx.x * blockDim.x + threadIdx.x;
    if (blockIdx.x == 0) {
        __shared__ int nz;
        if (threadIdx.x == 0) nz = 0;
        __syncthreads();
        for (int k = threadIdx.x; k < 4096; k += blockDim.x)
            if (w[2 * k + 1] != 0) nz = 1;
        __syncthreads();
        if (threadIdx.x == 0) g_is64 = nz ? 0 : 1;
    }
    if (i < NBINS) g_bins[i] = 0;
    if (i < NUM_NODES) {
        float xv = x[i];
        g_curA[i] = xv;
        g_surv[i] = 1.0f - xv;
        g_acc[i]  = 0.0f;
    }
}

// ---------------------------------------------------------------------------
// Convert + histogram + rank, grid-stride ILP=8 (coalesced within each batch,
// 8 independent load->atomic chains in flight per thread).
// ---------------------------------------------------------------------------
__device__ __forceinline__ void conv_one(const void* eidx, int is64, int i) {
    int s, d;
    if (is64) {
        const long long* e = (const long long*)eidx;
        s = (int)e[i];
        d = (int)e[NUM_EDGES + i];
    } else {
        const int* e = (const int*)eidx;
        s = e[i];
        d = e[NUM_EDGES + i];
    }
    s = min(max(s, 0), NUM_NODES - 1);
    d = min(max(d, 0), NUM_NODES - 1);
    int tile = d / TILE;
    int dl   = d - tile * TILE;
    int bin  = tile * NUM_NODES + s;
    unsigned rank = (unsigned)atomicAdd(&g_bins[bin], 1) & ((1u << RANK_BITS) - 1u);
    g_edges[i] = make_uint2(((unsigned)bin << RANK_BITS) | rank,
                            (unsigned)((s << 14) | dl));
}

__global__ void convert_hist_kernel(const void* __restrict__ eidx) {
    int t = blockIdx.x * blockDim.x + threadIdx.x;
    if (t >= GSTRIDE) return;
    int is64 = g_is64;
    #pragma unroll
    for (int k = 0; k < ILP; k++) conv_one(eidx, is64, t + k * GSTRIDE);
}

// ---------------------------------------------------------------------------
// 3-phase exclusive scan of g_bins -> g_binptr (block versions, R13-proven).
// ---------------------------------------------------------------------------
__global__ void scan1_kernel() {
    __shared__ int s[SCAN_BLK];
    int tid = threadIdx.x;
    int i = blockIdx.x * SCAN_BLK + tid;
    int v = (i < NBINS) ? g_bins[i] : 0;
    s[tid] = v;
    __syncthreads();
    #pragma unroll
    for (int o = 1; o < SCAN_BLK; o <<= 1) {
        int t = (tid >= o) ? s[tid - o] : 0;
        __syncthreads();
        s[tid] += t;
        __syncthreads();
    }
    if (i < NBINS) g_binptr[i] = s[tid] - v;   // exclusive, sans block offset
    if (tid == SCAN_BLK - 1) g_blocksum[blockIdx.x] = s[tid];
}

__global__ void scan2_kernel() {
    __shared__ int s[SCAN_BLK];
    int tid = threadIdx.x;
    int v = (tid < NSB) ? g_blocksum[tid] : 0;
    s[tid] = v;
    __syncthreads();
    #pragma unroll
    for (int o = 1; o < SCAN_BLK; o <<= 1) {
        int t = (tid >= o) ? s[tid - o] : 0;
        __syncthreads();
        s[tid] += t;
        __syncthreads();
    }
    if (tid < NSB) g_blocksum[tid] = s[tid] - v;  // exclusive block offsets
    if (tid == 0) g_binptr[NBINS] = NUM_EDGES;
}

__global__ void scan3_kernel() {
    int i = blockIdx.x * blockDim.x + threadIdx.x;
    if (i >= NBINS) return;
    g_binptr[i] += g_blocksum[i / SCAN_BLK];
}

// ---------------------------------------------------------------------------
// Atomic-free scatter, grid-stride ILP=8: pos = binptr[bin] + rank.
// ---------------------------------------------------------------------------
__device__ __forceinline__ void scat_one(const float* probs, int i) {
    uint2 e = g_edges[i];
    int bin  = (int)(e.x >> RANK_BITS);
    int rank = (int)(e.x & ((1u << RANK_BITS) - 1u));
    int pos  = g_binptr[bin] + rank;
    g_sp2[pos] = make_uint2(e.y, (unsigned)__float_as_int(probs[i]));
}

__global__ void scatter_kernel(const float* __restrict__ probs) {
    int t = blockIdx.x * blockDim.x + threadIdx.x;
    if (t >= GSTRIDE) return;
    #pragma unroll
    for (int k = 0; k < ILP; k++) scat_one(probs, t + k * GSTRIDE);
}

// ---------------------------------------------------------------------------
// Per-step edge pass: one dst tile per CTA group, smem accumulation.
// 2 edges per LDG.128; loop unrolled x4 with all loads issued up front (MLP).
// ---------------------------------------------------------------------------
__device__ __forceinline__ void process_edge(unsigned k, unsigned p,
                                             const float* cur, float* acc) {
    int src = (int)(k >> 14);
    int dl  = (int)(k & 16383u);
    atomicAdd(&acc[dl], __ldg(&cur[src]) * __int_as_float((int)p));
}

__global__ void __launch_bounds__(STEP_TPB)
spmv_tile_kernel(int step) {
    __shared__ float acc[TILE];
    int tile = blockIdx.x / CTAS_PER_TILE;
    int sub  = blockIdx.x % CTAS_PER_TILE;

    for (int i = threadIdx.x; i < TILE; i += STEP_TPB) acc[i] = 0.0f;
    __syncthreads();

    const float* cur = (step & 1) ? g_curB : g_curA;

    int start = g_binptr[tile * NUM_NODES];
    int end   = g_binptr[(tile + 1) * NUM_NODES];
    int n = end - start;
    int per = (n + CTAS_PER_TILE - 1) / CTAS_PER_TILE;
    int a = start + sub * per;
    int b = min(a + per, end);
    if (a > b) a = b;

    // peel to an even-even [a,b) range; threads 0/1 handle the odd ends
    int head = -1, tail = -1;
    if (a < b && (a & 1)) { head = a; a++; }
    if (a < b && ((b - a) & 1)) { tail = b - 1; b--; }
    if (threadIdx.x == 0 && head >= 0) {
        uint2 e = g_sp2[head];
        process_edge(e.x, e.y, cur, acc);
    }
    if (threadIdx.x == 1 && tail >= 0) {
        uint2 e = g_sp2[tail];
        process_edge(e.x, e.y, cur, acc);
    }

    // unrolled x4: issue all 16B loads before any atomics (MLP=4 on stream)
    const int S = STEP_TPB * 2;
    for (int j = a + threadIdx.x * 2; j < b; j += S * 4) {
        int j1 = j + S, j2 = j + 2 * S, j3 = j + 3 * S;
        bool h1 = (j1 < b), h2 = (j2 < b), h3 = (j3 < b);
        uint4 e0 = *reinterpret_cast<const uint4*>(&g_sp2[j]);
        uint4 e1 = h1 ? *reinterpret_cast<const uint4*>(&g_sp2[j1])
                      : make_uint4(0u, 0u, 0u, 0u);
        uint4 e2 = h2 ? *reinterpret_cast<const uint4*>(&g_sp2[j2])
                      : make_uint4(0u, 0u, 0u, 0u);
        uint4 e3 = h3 ? *reinterpret_cast<const uint4*>(&g_sp2[j3])
                      : make_uint4(0u, 0u, 0u, 0u);
        process_edge(e0.x, e0.y, cur, acc);
        process_edge(e0.z, e0.w, cur, acc);
        if (h1) { process_edge(e1.x, e1.y, cur, acc);
                  process_edge(e1.z, e1.w, cur, acc); }
        if (h2) { process_edge(e2.x, e2.y, cur, acc);
                  process_edge(e2.z, e2.w, cur, acc); }
        if (h3) { process_edge(e3.x, e3.y, cur, acc);
                  process_edge(e3.z, e3.w, cur, acc); }
    }
    __syncthreads();

    int base = tile * TILE;
    for (int i = threadIdx.x; i < TILE; i += STEP_TPB) {
        float v = acc[i];
        if (v != 0.0f) atomicAdd(&g_acc[base + i], v);
    }
}

// ---------------------------------------------------------------------------
// Per-step node pass: cur' = scale*acc + bias; surv *= (1-cur'); acc = 0.
// Buffer parity resolved in device code (host &symbol is invalid).
// ---------------------------------------------------------------------------
__global__ void node_kernel(const float* __restrict__ td,
                            const float* __restrict__ ew,
                            const float* __restrict__ nb,
                            int step, int is_last,
                            float* __restrict__ out) {
    int n = blockIdx.x * blockDim.x + threadIdx.x;
    if (n >= NUM_NODES) return;

    float* curn = (step & 1) ? g_curA : g_curB;

    float tdv = td[step];
    float scale = ew[step] * expf(-(tdv * tdv));
    float c = scale * g_acc[n] + nb[0];
    g_acc[n] = 0.0f;
    curn[n] = c;
    float sv = g_surv[n] * (1.0f - c);
    g_surv[n] = sv;
    if (is_last) {
        float fi = 1.0f - sv;
        out[n] = fminf(fmaxf(fi, 0.0f), 1.0f);
    }
}

// ---------------------------------------------------------------------------
// Launch
// ---------------------------------------------------------------------------
extern "C" void kernel_launch(void* const* d_in, const int* in_sizes, int n_in,
                              void* d_out, int out_size) {
    const float* x     = (const float*)d_in[0];
    const void*  eidx  = d_in[1];
    const float* probs = (const float*)d_in[2];
    const float* td    = (const float*)d_in[3];
    const float* nb    = (const float*)d_in[4];
    const float* ew    = (const float*)d_in[5];
    float*       out   = (float*)d_out;

    const int TB = 256;
    int gblocks = (GSTRIDE + TB - 1) / TB;
    int bblocks = (NBINS + TB - 1) / TB;

    prep_kernel<<<bblocks, TB>>>((const int*)eidx, x);
    convert_hist_kernel<<<gblocks, TB>>>(eidx);
    scan1_kernel<<<NSB, SCAN_BLK>>>();
    scan2_kernel<<<1, SCAN_BLK>>>();
    scan3_kernel<<<bblocks, TB>>>();
    scatter_kernel<<<gblocks, TB>>>(probs);

    int nblocks = (NUM_NODES + TB - 1) / TB;
    for (int step = 0; step < NUM_STEPS; step++) {
        spmv_tile_kernel<<<NTILES * CTAS_PER_TILE, STEP_TPB>>>(step);
        node_kernel<<<nblocks, TB>>>(td, ew, nb, step,
                                     (step == NUM_STEPS - 1) ? 1 : 0, out);
    }
}

// round 17
// speedup vs baseline: 1.0425x; 1.0425x over previous
#include <cuda_runtime.h>

#define NUM_NODES 100000
#define NUM_EDGES 6400000
#define NUM_STEPS 10

#define TILE 10000                 // dst nodes per tile (40KB smem acc in spmv)
#define NTILES 10
#define CTAS_PER_TILE 15           // 150 CTAs (R5/R10-proven)
#define STEP_TPB 1024

#define SRC_SHIFT 2                // bin groups 4 srcs (16B line) - spmv locality kept
#define NSRCG 25000                // 100000 >> 2
#define NBINS (NTILES * NSRCG)     // 250,000 bins: key = dst_tile*NSRCG + (src>>2)
#define RANK_BITS 9                // bin<<9|rank : bin<2^18, rank~Poisson(25.6)<512
#define SCAN_BLK 1024
#define NSB ((NBINS + SCAN_BLK - 1) / SCAN_BLK)   // 245

#define ILP 4
#define GSTRIDE (NUM_EDGES / ILP)  // 1,600,000 threads; edges {t, t+G, t+2G, t+3G}

// Scratch (allocation-free rule: __device__ globals)
__device__ uint2 g_edges[NUM_EDGES];              // {bin<<9|rank, src<<14|dl}
__device__ __align__(16) uint2 g_sp2[NUM_EDGES];  // {packed, prob-bits}, sorted
__device__ int   g_bins[NBINS];
__device__ int   g_binptr[NBINS + 1];
__device__ int   g_blocksum[NSB];
__device__ float g_curA[NUM_NODES];
__device__ float g_curB[NUM_NODES];
__device__ float g_surv[NUM_NODES];
__device__ float g_acc[NUM_NODES];
__device__ int   g_is64;

// ---------------------------------------------------------------------------
// Fused prep: detect int64-vs-int32 (block 0), zero bins, init node state.
// ---------------------------------------------------------------------------
__global__ void prep_kernel(const int* __restrict__ w, const float* __restrict__ x) {
    int i = blockIdx.x * blockDim.x + threadIdx.x;
    if (blockIdx.x == 0) {
        __shared__ int nz;
        if (threadIdx.x == 0) nz = 0;
        __syncthreads();
        for (int k = threadIdx.x; k < 4096; k += blockDim.x)
            if (w[2 * k + 1] != 0) nz = 1;
        __syncthreads();
        if (threadIdx.x == 0) g_is64 = nz ? 0 : 1;
    }
    if (i < NBINS) g_bins[i] = 0;
    if (i < NUM_NODES) {
        float xv = x[i];
        g_curA[i] = xv;
        g_surv[i] = 1.0f - xv;
        g_acc[i]  = 0.0f;
    }
}

// ---------------------------------------------------------------------------
// Convert + histogram + rank, grid-stride ILP=4 (coalesced within each batch,
// 4 independent load->atomic chains). Hist atomic's return value IS the
// edge's permanent within-bin rank -> scatter needs no atomics.
// bin = dst_tile*NSRCG + (src>>2) ; payload keeps EXACT src: src<<14 | dl
// ---------------------------------------------------------------------------
__device__ __forceinline__ void conv_one(const void* eidx, int is64, int i) {
    int s, d;
    if (is64) {
        const long long* e = (const long long*)eidx;
        s = (int)e[i];
        d = (int)e[NUM_EDGES + i];
    } else {
        const int* e = (const int*)eidx;
        s = e[i];
        d = e[NUM_EDGES + i];
    }
    s = min(max(s, 0), NUM_NODES - 1);
    d = min(max(d, 0), NUM_NODES - 1);
    int tile = d / TILE;
    int dl   = d - tile * TILE;
    int bin  = tile * NSRCG + (s >> SRC_SHIFT);
    unsigned rank = (unsigned)atomicAdd(&g_bins[bin], 1) & ((1u << RANK_BITS) - 1u);
    g_edges[i] = make_uint2(((unsigned)bin << RANK_BITS) | rank,
                            (unsigned)((s << 14) | dl));
}

__global__ void convert_hist_kernel(const void* __restrict__ eidx) {
    int t = blockIdx.x * blockDim.x + threadIdx.x;
    if (t >= GSTRIDE) return;
    int is64 = g_is64;
    #pragma unroll
    for (int k = 0; k < ILP; k++) conv_one(eidx, is64, t + k * GSTRIDE);
}

// ---------------------------------------------------------------------------
// 3-phase exclusive scan of g_bins -> g_binptr (block versions, proven).
// ---------------------------------------------------------------------------
__global__ void scan1_kernel() {
    __shared__ int s[SCAN_BLK];
    int tid = threadIdx.x;
    int i = blockIdx.x * SCAN_BLK + tid;
    int v = (i < NBINS) ? g_bins[i] : 0;
    s[tid] = v;
    __syncthreads();
    #pragma unroll
    for (int o = 1; o < SCAN_BLK; o <<= 1) {
        int t = (tid >= o) ? s[tid - o] : 0;
        __syncthreads();
        s[tid] += t;
        __syncthreads();
    }
    if (i < NBINS) g_binptr[i] = s[tid] - v;   // exclusive, sans block offset
    if (tid == SCAN_BLK - 1) g_blocksum[blockIdx.x] = s[tid];
}

__global__ void scan2_kernel() {
    __shared__ int s[SCAN_BLK];
    int tid = threadIdx.x;
    int v = (tid < NSB) ? g_blocksum[tid] : 0;
    s[tid] = v;
    __syncthreads();
    #pragma unroll
    for (int o = 1; o < SCAN_BLK; o <<= 1) {
        int t = (tid >= o) ? s[tid - o] : 0;
        __syncthreads();
        s[tid] += t;
        __syncthreads();
    }
    if (tid < NSB) g_blocksum[tid] = s[tid] - v;  // exclusive block offsets
    if (tid == 0) g_binptr[NBINS] = NUM_EDGES;
}

__global__ void scan3_kernel() {
    int i = blockIdx.x * blockDim.x + threadIdx.x;
    if (i >= NBINS) return;
    g_binptr[i] += g_blocksum[i / SCAN_BLK];
}

// ---------------------------------------------------------------------------
// Atomic-free scatter, grid-stride ILP=4: pos = binptr[bin] + rank.
// ---------------------------------------------------------------------------
__device__ __forceinline__ void scat_one(const float* probs, int i) {
    uint2 e = g_edges[i];
    int bin  = (int)(e.x >> RANK_BITS);
    int rank = (int)(e.x & ((1u << RANK_BITS) - 1u));
    int pos  = g_binptr[bin] + rank;
    g_sp2[pos] = make_uint2(e.y, (unsigned)__float_as_int(probs[i]));
}

__global__ void scatter_kernel(const float* __restrict__ probs) {
    int t = blockIdx.x * blockDim.x + threadIdx.x;
    if (t >= GSTRIDE) return;
    #pragma unroll
    for (int k = 0; k < ILP; k++) scat_one(probs, t + k * GSTRIDE);
}

// ---------------------------------------------------------------------------
// Per-step edge pass (R15-proven): one dst tile per CTA group, smem
// accumulation; 2 edges per LDG.128, unrolled x2 with loads up front (MLP=2).
// ---------------------------------------------------------------------------
__device__ __forceinline__ void process_edge(unsigned k, unsigned p,
                                             const float* cur, float* acc) {
    int src = (int)(k >> 14);
    int dl  = (int)(k & 16383u);
    atomicAdd(&acc[dl], __ldg(&cur[src]) * __int_as_float((int)p));
}

__global__ void __launch_bounds__(STEP_TPB)
spmv_tile_kernel(int step) {
    __shared__ float acc[TILE];
    int tile = blockIdx.x / CTAS_PER_TILE;
    int sub  = blockIdx.x % CTAS_PER_TILE;

    for (int i = threadIdx.x; i < TILE; i += STEP_TPB) acc[i] = 0.0f;
    __syncthreads();

    const float* cur = (step & 1) ? g_curB : g_curA;

    int start = g_binptr[tile * NSRCG];
    int end   = g_binptr[(tile + 1) * NSRCG];
    int n = end - start;
    int per = (n + CTAS_PER_TILE - 1) / CTAS_PER_TILE;
    int a = start + sub * per;
    int b = min(a + per, end);
    if (a > b) a = b;

    // peel to an even-even [a,b) range; threads 0/1 handle the odd ends
    int head = -1, tail = -1;
    if (a < b && (a & 1)) { head = a; a++; }
    if (a < b && ((b - a) & 1)) { tail = b - 1; b--; }
    if (threadIdx.x == 0 && head >= 0) {
        uint2 e = g_sp2[head];
        process_edge(e.x, e.y, cur, acc);
    }
    if (threadIdx.x == 1 && tail >= 0) {
        uint2 e = g_sp2[tail];
        process_edge(e.x, e.y, cur, acc);
    }

    // unrolled x2: issue both 16B loads before any atomics (MLP=2 on stream)
    for (int j = a + threadIdx.x * 2; j < b; j += STEP_TPB * 4) {
        int j2 = j + STEP_TPB * 2;
        bool has2 = (j2 < b);
        uint4 e0 = *reinterpret_cast<const uint4*>(&g_sp2[j]);
        uint4 e1 = has2 ? *reinterpret_cast<const uint4*>(&g_sp2[j2])
                        : make_uint4(0u, 0u, 0u, 0u);
        process_edge(e0.x, e0.y, cur, acc);
        process_edge(e0.z, e0.w, cur, acc);
        if (has2) {
            process_edge(e1.x, e1.y, cur, acc);
            process_edge(e1.z, e1.w, cur, acc);
        }
    }
    __syncthreads();

    int base = tile * TILE;
    for (int i = threadIdx.x; i < TILE; i += STEP_TPB) {
        float v = acc[i];
        if (v != 0.0f) atomicAdd(&g_acc[base + i], v);
    }
}

// ---------------------------------------------------------------------------
// Per-step node pass: cur' = scale*acc + bias; surv *= (1-cur'); acc = 0.
// Buffer parity resolved in device code (host &symbol is invalid).
// ---------------------------------------------------------------------------
__global__ void node_kernel(const float* __restrict__ td,
                            const float* __restrict__ ew,
                            const float* __restrict__ nb,
                            int step, int is_last,
                            float* __restrict__ out) {
    int n = blockIdx.x * blockDim.x + threadIdx.x;
    if (n >= NUM_NODES) return;

    float* curn = (step & 1) ? g_curA : g_curB;

    float tdv = td[step];
    float scale = ew[step] * expf(-(tdv * tdv));
    float c = scale * g_acc[n] + nb[0];
    g_acc[n] = 0.0f;
    curn[n] = c;
    float sv = g_surv[n] * (1.0f - c);
    g_surv[n] = sv;
    if (is_last) {
        float fi = 1.0f - sv;
        out[n] = fminf(fmaxf(fi, 0.0f), 1.0f);
    }
}

// ---------------------------------------------------------------------------
// Launch
// ---------------------------------------------------------------------------
extern "C" void kernel_launch(void* const* d_in, const int* in_sizes, int n_in,
                              void* d_out, int out_size) {
    const float* x     = (const float*)d_in[0];
    const void*  eidx  = d_in[1];
    const float* probs = (const float*)d_in[2];
    const float* td    = (const float*)d_in[3];
    const float* nb    = (const float*)d_in[4];
    const float* ew    = (const float*)d_in[5];
    float*       out   = (float*)d_out;

    const int TB = 256;
    int gblocks = (GSTRIDE + TB - 1) / TB;
    int bblocks = (NBINS + TB - 1) / TB;
    int pblocks = (NUM_NODES + TB - 1) / TB;   // >= bblocks? no: prep covers both
    int prepblocks = (pblocks > bblocks) ? pblocks : bblocks;

    prep_kernel<<<prepblocks, TB>>>((const int*)eidx, x);
    convert_hist_kernel<<<gblocks, TB>>>(eidx);
    scan1_kernel<<<NSB, SCAN_BLK>>>();
    scan2_kernel<<<1, SCAN_BLK>>>();
    scan3_kernel<<<bblocks, TB>>>();
    scatter_kernel<<<gblocks, TB>>>(probs);

    for (int step = 0; step < NUM_STEPS; step++) {
        spmv_tile_kernel<<<NTILES * CTAS_PER_TILE, STEP_TPB>>>(step);
        node_kernel<<<pblocks, TB>>>(td, ew, nb, step,
                                     (step == NUM_STEPS - 1) ? 1 : 0, out);
    }
}